// round 1
// baseline (speedup 1.0000x reference)
#include <cuda_runtime.h>
#include <cstdint>
#include <math.h>

#define N_NODES 50000
#define E_EDGES 800000
#define F_IN    128
#define HID     96
#define L_LAYERS 4

// ---------------- device scratch (no allocations allowed) ----------------
__device__ __align__(16) float    g_h   [N_NODES * HID];
__device__ __align__(16) float    g_hn  [N_NODES * HID];
__device__ __align__(16) float    g_xlxr[N_NODES * 2 * HID];   // stride 192: [0:96)=xl, [96:192)=xr
__device__ __align__(16) float    g_agg [N_NODES * HID];
__device__ __align__(16) float    g_alpha[E_EDGES];
__device__ __align__(16) float    g_aexp [E_EDGES];
__device__ __align__(16) unsigned g_menc [N_NODES];
__device__ __align__(16) float    g_s    [N_NODES];
__device__ __align__(16) int      g_src  [E_EDGES];
__device__ __align__(16) int      g_dst  [E_EDGES];
__device__ int g_is64;

// ---------------- helpers ----------------
__device__ __forceinline__ unsigned fenc(float f) {
    unsigned u = __float_as_uint(f);
    return (u & 0x80000000u) ? ~u : (u | 0x80000000u);
}
__device__ __forceinline__ float fdec(unsigned u) {
    return (u & 0x80000000u) ? __uint_as_float(u & 0x7fffffffu) : __uint_as_float(~u);
}

// ---------------- edge_index dtype sniff + int32 conversion ----------------
__global__ void detect_kernel(const int* ei32) {
    // If the tensor is int64 (values < 50000, non-negative), every odd int32
    // word (high half) is zero. If it's genuinely int32, odds of 8 zeros ~ 0.
    bool is64 = true;
    #pragma unroll
    for (int i = 0; i < 8; i++) if (ei32[2 * i + 1] != 0) is64 = false;
    g_is64 = is64 ? 1 : 0;
}

__global__ void convert_kernel(const void* ei) {
    int e = blockIdx.x * blockDim.x + threadIdx.x;
    if (e >= E_EDGES) return;
    if (g_is64) {
        const long long* p = (const long long*)ei;
        g_src[e] = (int)p[e];
        g_dst[e] = (int)p[E_EDGES + e];
    } else {
        const int* p = (const int*)ei;
        g_src[e] = p[e];
        g_dst[e] = p[E_EDGES + e];
    }
}

// ---------------- GEMM: C[nrows,CW] = A[nrows,K] @ [W1|W2] + [b1|b2] ----------------
// Tile: 64 rows x CW cols per block, 256 threads, 8 rows x (CW/32) cols per thread.
template <int K, int CW, int CW1>
__global__ void __launch_bounds__(256) gemm_kernel(
    const float* __restrict__ A,
    const float* __restrict__ W1, const float* __restrict__ W2,
    const float* __restrict__ b1, const float* __restrict__ b2,
    float* __restrict__ C, int nrows)
{
    constexpr int KCH = 32;
    constexpr int RPB = 64;
    constexpr int CPT = CW / 32;
    __shared__ float As[RPB * KCH];
    __shared__ float Ws[KCH * CW];

    const int tid = threadIdx.x;
    const int cx  = tid & 31;   // column lane (cols: cx + c*32)
    const int ry  = tid >> 5;   // row group (rows: ry + j*8)
    const int rowbase = blockIdx.x * RPB;

    float acc[8][CPT];
    #pragma unroll
    for (int j = 0; j < 8; j++)
        #pragma unroll
        for (int c = 0; c < CPT; c++) acc[j][c] = 0.f;

    for (int kc = 0; kc < K; kc += KCH) {
        // load A tile (64 x 32), zero-pad out-of-range rows
        #pragma unroll
        for (int i = 0; i < (RPB * KCH) / (256 * 4); i++) {
            int f4  = tid + i * 256;
            int row = f4 >> 3;              // / (KCH/4)
            int kk  = (f4 & 7) * 4;
            float4 v = make_float4(0.f, 0.f, 0.f, 0.f);
            int grow = rowbase + row;
            if (grow < nrows) v = *(const float4*)(A + (size_t)grow * K + kc + kk);
            *(float4*)(As + row * KCH + kk) = v;
        }
        // load W tile (32 x CW) from W1 / W2 halves
        #pragma unroll
        for (int i = 0; i < (KCH * CW) / (256 * 4); i++) {
            int f  = (tid + i * 256) * 4;
            int k  = f / CW;
            int c  = f % CW;
            float4 v;
            if (c < CW1) v = *(const float4*)(W1 + (size_t)(kc + k) * CW1 + c);
            else         v = *(const float4*)(W2 + (size_t)(kc + k) * (CW - CW1) + (c - CW1));
            *(float4*)(Ws + k * CW + c) = v;
        }
        __syncthreads();

        #pragma unroll 8
        for (int kk = 0; kk < KCH; kk++) {
            float a[8];
            #pragma unroll
            for (int j = 0; j < 8; j++) a[j] = As[(ry + j * 8) * KCH + kk];
            #pragma unroll
            for (int c = 0; c < CPT; c++) {
                float w = Ws[kk * CW + cx + c * 32];
                #pragma unroll
                for (int j = 0; j < 8; j++) acc[j][c] = fmaf(a[j], w, acc[j][c]);
            }
        }
        __syncthreads();
    }

    #pragma unroll
    for (int c = 0; c < CPT; c++) {
        int col = cx + c * 32;
        float bv = (col < CW1) ? b1[col] : b2[col - CW1];
        #pragma unroll
        for (int j = 0; j < 8; j++) {
            int grow = rowbase + ry + j * 8;
            if (grow < nrows) C[(size_t)grow * CW + col] = acc[j][c] + bv;
        }
    }
}

// ---------------- LayerNorm (+optional residual update) + ReLU ----------------
// warp per node, lane handles elements {lane, lane+32, lane+64}
__global__ void __launch_bounds__(256) ln_update_kernel(
    float* __restrict__ h, const float* __restrict__ agg,
    const float* __restrict__ bias,
    const float* __restrict__ g, const float* __restrict__ b,
    float* __restrict__ hn, int add)
{
    int warp = threadIdx.x >> 5;
    int lane = threadIdx.x & 31;
    int n = blockIdx.x * 8 + warp;
    if (n >= N_NODES) return;
    size_t base = (size_t)n * HID;

    float v[3];
    #pragma unroll
    for (int i = 0; i < 3; i++) {
        int k = lane + i * 32;
        float x = h[base + k];
        if (add) { x += agg[base + k] + bias[k]; h[base + k] = x; }
        v[i] = x;
    }
    float s = v[0] + v[1] + v[2];
    #pragma unroll
    for (int o = 16; o > 0; o >>= 1) s += __shfl_xor_sync(0xffffffffu, s, o);
    float mean = s * (1.0f / HID);

    float d[3], sq = 0.f;
    #pragma unroll
    for (int i = 0; i < 3; i++) { d[i] = v[i] - mean; sq = fmaf(d[i], d[i], sq); }
    #pragma unroll
    for (int o = 16; o > 0; o >>= 1) sq += __shfl_xor_sync(0xffffffffu, sq, o);
    float rstd = rsqrtf(sq * (1.0f / HID) + 1e-5f);

    #pragma unroll
    for (int i = 0; i < 3; i++) {
        int k = lane + i * 32;
        float o = fmaf(d[i] * rstd, g[k], b[k]);
        hn[base + k] = fmaxf(o, 0.f);
    }
}

// ---------------- edge pass 1: alpha + segment max ----------------
// 8 threads per edge, float4 per lane per 32-float chunk
__global__ void __launch_bounds__(256) edge_alpha_kernel(
    const float* __restrict__ ew,
    const float* __restrict__ We, const float* __restrict__ att)
{
    __shared__ float sWe[HID], sAtt[HID];
    if (threadIdx.x < HID) { sWe[threadIdx.x] = We[threadIdx.x]; sAtt[threadIdx.x] = att[threadIdx.x]; }
    __syncthreads();

    int gid  = blockIdx.x * blockDim.x + threadIdx.x;
    int e    = gid >> 3;
    int lane8 = gid & 7;
    if (e >= E_EDGES) return;

    int src = g_src[e];
    int dst = g_dst[e];
    float w = ew[e];
    const float* xl = g_xlxr + (size_t)src * 192;
    const float* xr = g_xlxr + (size_t)dst * 192 + 96;

    float part = 0.f;
    #pragma unroll
    for (int c = 0; c < 3; c++) {
        int k = c * 32 + lane8 * 4;
        float4 a  = *(const float4*)(xl + k);
        float4 b  = *(const float4*)(xr + k);
        float4 wv = *(const float4*)(sWe + k);
        float4 tv = *(const float4*)(sAtt + k);
        float e0 = a.x + b.x + w * wv.x; e0 = e0 > 0.f ? e0 : 0.2f * e0; part = fmaf(e0, tv.x, part);
        float e1 = a.y + b.y + w * wv.y; e1 = e1 > 0.f ? e1 : 0.2f * e1; part = fmaf(e1, tv.y, part);
        float e2 = a.z + b.z + w * wv.z; e2 = e2 > 0.f ? e2 : 0.2f * e2; part = fmaf(e2, tv.z, part);
        float e3 = a.w + b.w + w * wv.w; e3 = e3 > 0.f ? e3 : 0.2f * e3; part = fmaf(e3, tv.w, part);
    }
    part += __shfl_xor_sync(0xffffffffu, part, 4);
    part += __shfl_xor_sync(0xffffffffu, part, 2);
    part += __shfl_xor_sync(0xffffffffu, part, 1);

    if (lane8 == 0) {
        g_alpha[e] = part;
        atomicMax(&g_menc[dst], fenc(part));
    }
}

// ---------------- edge pass 2: exp + segment sum ----------------
__global__ void __launch_bounds__(256) edge_soft_kernel()
{
    int e = blockIdx.x * blockDim.x + threadIdx.x;
    if (e >= E_EDGES) return;
    int dst = g_dst[e];
    float m = fdec(g_menc[dst]);
    float p = expf(g_alpha[e] - m);
    g_aexp[e] = p;
    atomicAdd(&g_s[dst], p);
}

// ---------------- edge pass 3: weighted aggregation (vector red.add) ----------------
__global__ void __launch_bounds__(256) edge_agg_kernel()
{
    int gid  = blockIdx.x * blockDim.x + threadIdx.x;
    int e    = gid >> 3;
    int lane8 = gid & 7;
    if (e >= E_EDGES) return;

    int src = g_src[e];
    int dst = g_dst[e];
    float w = g_aexp[e] / (g_s[dst] + 1e-16f);
    const float* xl = g_xlxr + (size_t)src * 192;
    float* out = g_agg + (size_t)dst * HID;

    #pragma unroll
    for (int c = 0; c < 3; c++) {
        int k = c * 32 + lane8 * 4;
        float4 a = *(const float4*)(xl + k);
        float x0 = a.x * w, x1 = a.y * w, x2 = a.z * w, x3 = a.w * w;
        asm volatile("red.global.add.v4.f32 [%0], {%1,%2,%3,%4};"
                     :: "l"(out + k), "f"(x0), "f"(x1), "f"(x2), "f"(x3) : "memory");
    }
}

// ---------------- final FC: out[n] = dot(hn[n], fcW) + fcb ----------------
__global__ void __launch_bounds__(256) fc_kernel(
    const float* __restrict__ fcW, const float* __restrict__ fcb,
    float* __restrict__ out)
{
    int warp = threadIdx.x >> 5;
    int lane = threadIdx.x & 31;
    int n = blockIdx.x * 8 + warp;
    if (n >= N_NODES) return;
    size_t base = (size_t)n * HID;
    float acc = 0.f;
    #pragma unroll
    for (int i = 0; i < 3; i++) {
        int k = lane + i * 32;
        acc = fmaf(g_hn[base + k], fcW[k], acc);
    }
    #pragma unroll
    for (int o = 16; o > 0; o >>= 1) acc += __shfl_xor_sync(0xffffffffu, acc, o);
    if (lane == 0) out[n] = acc + fcb[0];
}

// ---------------- launch ----------------
extern "C" void kernel_launch(void* const* d_in, const int* in_sizes, int n_in,
                              void* d_out, int out_size)
{
    const float*     x    = (const float*)d_in[0];
    const void*      ei   = (const void*) d_in[1];
    const float*     ew   = (const float*)d_in[2];
    const float*     encW = (const float*)d_in[3];
    const float*     encb = (const float*)d_in[4];
    const float*     Wl   = (const float*)d_in[5];
    const float*     bl   = (const float*)d_in[6];
    const float*     Wr   = (const float*)d_in[7];
    const float*     br   = (const float*)d_in[8];
    const float*     We   = (const float*)d_in[9];
    const float*     att  = (const float*)d_in[10];
    const float*     bias = (const float*)d_in[11];
    const float*     lng  = (const float*)d_in[12];
    const float*     lnb  = (const float*)d_in[13];
    const float*     lnfg = (const float*)d_in[14];
    const float*     lnfb = (const float*)d_in[15];
    const float*     fcW  = (const float*)d_in[16];
    const float*     fcb  = (const float*)d_in[17];
    float*           out  = (float*)d_out;

    void *p_h, *p_hn, *p_xlxr, *p_agg, *p_menc, *p_s;
    cudaGetSymbolAddress(&p_h,    g_h);
    cudaGetSymbolAddress(&p_hn,   g_hn);
    cudaGetSymbolAddress(&p_xlxr, g_xlxr);
    cudaGetSymbolAddress(&p_agg,  g_agg);
    cudaGetSymbolAddress(&p_menc, g_menc);
    cudaGetSymbolAddress(&p_s,    g_s);

    const int gemm_blocks = (N_NODES + 63) / 64;
    const int node_blocks = (N_NODES + 7) / 8;          // warp per node
    const int edge8_blocks = (E_EDGES * 8) / 256;       // 25000
    const int edge1_blocks = (E_EDGES + 255) / 256;     // 3125

    // edge index -> int32 src/dst
    detect_kernel<<<1, 1>>>((const int*)ei);
    convert_kernel<<<edge1_blocks, 256>>>(ei);

    // encoder + first LN
    gemm_kernel<F_IN, HID, HID><<<gemm_blocks, 256>>>(
        x, encW, encW, encb, encb, (float*)p_h, N_NODES);
    ln_update_kernel<<<node_blocks, 256>>>(
        (float*)p_h, (const float*)p_agg, bias, lng, lnb, (float*)p_hn, 0);

    for (int i = 0; i < L_LAYERS; i++) {
        // xl | xr
        gemm_kernel<HID, 2 * HID, HID><<<gemm_blocks, 256>>>(
            (const float*)p_hn, Wl + (size_t)i * HID * HID, Wr + (size_t)i * HID * HID,
            bl + i * HID, br + i * HID, (float*)p_xlxr, N_NODES);

        cudaMemsetAsync(p_menc, 0, N_NODES * sizeof(unsigned));
        cudaMemsetAsync(p_s,    0, N_NODES * sizeof(float));
        cudaMemsetAsync(p_agg,  0, (size_t)N_NODES * HID * sizeof(float));

        edge_alpha_kernel<<<edge8_blocks, 256>>>(ew, We + i * HID, att + i * HID);
        edge_soft_kernel<<<edge1_blocks, 256>>>();
        edge_agg_kernel<<<edge8_blocks, 256>>>();

        const float* gnext = (i < L_LAYERS - 1) ? (lng + (i + 1) * HID) : lnfg;
        const float* bnext = (i < L_LAYERS - 1) ? (lnb + (i + 1) * HID) : lnfb;
        ln_update_kernel<<<node_blocks, 256>>>(
            (float*)p_h, (const float*)p_agg, bias + i * HID, gnext, bnext, (float*)p_hn, 1);
    }

    fc_kernel<<<node_blocks, 256>>>(fcW, fcb, out);
}